// round 7
// baseline (speedup 1.0000x reference)
#include <cuda_runtime.h>
#include <math.h>

#define NN_CAP 100000
#define EE_CAP 1600000
#define D      64
#define ED     16
#define CHUNK  512

// Scratch (no allocations allowed) — same footprint class as the passing R3.
__device__ float g_xp[NN_CAP * D];        // projected nodes (25.6 MB)
__device__ int   g_hist[NN_CAP];          // per-node in-degree
__device__ int   g_pos[NN_CAP];           // per-node fill cursor
__device__ int   g_off[NN_CAP + 1];       // CSR offsets
__device__ int   g_partial[256];          // chunk partial sums
__device__ int2  g_sedge[EE_CAP];         // CSR payload: (col, gate bits) (12.8 MB)

// ---------------------------------------------------------------------------
// K0: zero histogram + cursors
// ---------------------------------------------------------------------------
__global__ void init_kernel(int n_nodes) {
    int i = blockIdx.x * blockDim.x + threadIdx.x;
    if (i < n_nodes) { g_hist[i] = 0; g_pos[i] = 0; }
}

// ---------------------------------------------------------------------------
// K1: xp = x @ W_node^T + b_node   (x:[N,64], W:[64,64] row-major [o][i])
// ---------------------------------------------------------------------------
__global__ void __launch_bounds__(256) gemm_xp_kernel(
        const float* __restrict__ x,
        const float* __restrict__ W,
        const float* __restrict__ b,
        int n_nodes) {
    __shared__ float Ws[64][68];  // Ws[i][o]
    __shared__ float Xs[64][68];  // Xs[i][n]

    const int tid = threadIdx.x;
    const int node0 = blockIdx.x * 64;

    #pragma unroll
    for (int t = tid; t < 64 * 16; t += 256) {
        int o = t >> 4;
        int i4 = (t & 15) << 2;
        float4 w = *reinterpret_cast<const float4*>(&W[o * 64 + i4]);
        Ws[i4 + 0][o] = w.x; Ws[i4 + 1][o] = w.y;
        Ws[i4 + 2][o] = w.z; Ws[i4 + 3][o] = w.w;
    }
    #pragma unroll
    for (int t = tid; t < 64 * 16; t += 256) {
        int n = t >> 4;
        int i4 = (t & 15) << 2;
        int gn = node0 + n;
        float4 v = make_float4(0.f, 0.f, 0.f, 0.f);
        if (gn < n_nodes)
            v = *reinterpret_cast<const float4*>(&x[gn * 64 + i4]);
        Xs[i4 + 0][n] = v.x; Xs[i4 + 1][n] = v.y;
        Xs[i4 + 2][n] = v.z; Xs[i4 + 3][n] = v.w;
    }
    __syncthreads();

    const int tx = tid & 15;
    const int ty = tid >> 4;
    const int o0 = ty * 4;
    const int n0 = tx * 4;

    float acc[4][4];
    #pragma unroll
    for (int a = 0; a < 4; a++)
        #pragma unroll
        for (int c = 0; c < 4; c++) acc[a][c] = 0.0f;

    #pragma unroll
    for (int i = 0; i < 64; i++) {
        float4 wv = *reinterpret_cast<float4*>(&Ws[i][o0]);
        float4 xv = *reinterpret_cast<float4*>(&Xs[i][n0]);
        float wr[4] = {wv.x, wv.y, wv.z, wv.w};
        float xr[4] = {xv.x, xv.y, xv.z, xv.w};
        #pragma unroll
        for (int a = 0; a < 4; a++)
            #pragma unroll
            for (int c = 0; c < 4; c++)
                acc[a][c] = fmaf(xr[a], wr[c], acc[a][c]);
    }

    float4 bv = *reinterpret_cast<const float4*>(&b[o0]);
    #pragma unroll
    for (int a = 0; a < 4; a++) {
        int gn = node0 + n0 + a;
        if (gn < n_nodes) {
            float4 r;
            r.x = acc[a][0] + bv.x; r.y = acc[a][1] + bv.y;
            r.z = acc[a][2] + bv.z; r.w = acc[a][3] + bv.w;
            *reinterpret_cast<float4*>(&g_xp[gn * 64 + o0]) = r;
        }
    }
}

// ---------------------------------------------------------------------------
// K2: histogram of destination rows
// ---------------------------------------------------------------------------
__global__ void hist_kernel(const int* __restrict__ ei, int n_edges, int n_nodes) {
    int e = blockIdx.x * blockDim.x + threadIdx.x;
    if (e >= n_edges) return;
    int row = __ldg(&ei[e]);
    int col = __ldg(&ei[n_edges + e]);
    if ((unsigned)row >= (unsigned)n_nodes || (unsigned)col >= (unsigned)n_nodes)
        return;
    atomicAdd(&g_hist[row], 1);
}

// ---------------------------------------------------------------------------
// K3a: per-chunk sums (warp-shfl reduce; minimal syncs)
// ---------------------------------------------------------------------------
__global__ void scan_partial_kernel(int n_nodes) {
    int i = blockIdx.x * CHUNK + threadIdx.x;
    int v = (i < n_nodes) ? g_hist[i] : 0;
    #pragma unroll
    for (int o = 16; o; o >>= 1) v += __shfl_down_sync(0xffffffffu, v, o);
    __shared__ int s[16];
    if ((threadIdx.x & 31) == 0) s[threadIdx.x >> 5] = v;
    __syncthreads();
    if (threadIdx.x < 16) {
        int t = s[threadIdx.x];
        #pragma unroll
        for (int o = 8; o; o >>= 1) t += __shfl_down_sync(0xffffu, t, o, 16);
        if (threadIdx.x == 0) g_partial[blockIdx.x] = t;
    }
}

// ---------------------------------------------------------------------------
// K3b: final scan. Each block: warp-scan local chunk + inline prefix of the
// (<=196) chunk partials. Writes g_off[0..n] including total.
// ---------------------------------------------------------------------------
__global__ void scan_final_kernel(int n_nodes) {
    const int tid = threadIdx.x;
    const int bid = blockIdx.x;
    const int lane = tid & 31;
    const int wid = tid >> 5;
    int i = bid * CHUNK + tid;
    int v = (i < n_nodes) ? g_hist[i] : 0;

    // inclusive warp scan of v
    int x = v;
    #pragma unroll
    for (int o = 1; o < 32; o <<= 1) {
        int y = __shfl_up_sync(0xffffffffu, x, o);
        if (lane >= o) x += y;
    }

    __shared__ int wsum[16];
    __shared__ int blockpref;
    if (lane == 31) wsum[wid] = x;
    if (tid < 32) {
        int acc = 0;
        for (int k = lane; k < bid; k += 32) acc += g_partial[k];
        #pragma unroll
        for (int o = 16; o; o >>= 1) acc += __shfl_down_sync(0xffffffffu, acc, o);
        if (lane == 0) blockpref = acc;
    }
    __syncthreads();
    if (tid < 16) {
        int t = wsum[tid];
        #pragma unroll
        for (int o = 1; o < 16; o <<= 1) {
            int y = __shfl_up_sync(0xffffu, t, o, 16);
            if (tid >= o) t += y;
        }
        wsum[tid] = t;  // inclusive over warps
    }
    __syncthreads();

    int warppref = (wid == 0) ? 0 : wsum[wid - 1];
    int incl = x + warppref + blockpref;
    int excl = incl - v;
    if (i < n_nodes) {
        g_off[i] = excl;
        if (i == n_nodes - 1) g_off[n_nodes] = incl;
    }
}

// ---------------------------------------------------------------------------
// K4: permute — compute gate per edge, write (col, gate) into CSR slot.
// ---------------------------------------------------------------------------
__global__ void __launch_bounds__(256) permute_kernel(
        const int* __restrict__ ei,
        const float* __restrict__ ef,
        const float* __restrict__ We,
        const float* __restrict__ be,
        int n_edges, int n_nodes) {
    int e = blockIdx.x * blockDim.x + threadIdx.x;
    if (e >= n_edges) return;
    int row = __ldg(&ei[e]);
    int col = __ldg(&ei[n_edges + e]);
    if ((unsigned)row >= (unsigned)n_nodes || (unsigned)col >= (unsigned)n_nodes)
        return;

    const float4* efp = reinterpret_cast<const float4*>(&ef[(long long)e * ED]);
    const float4* wep = reinterpret_cast<const float4*>(We);
    float dot = 0.0f;
    #pragma unroll
    for (int k = 0; k < 4; k++) {
        float4 a = __ldg(&efp[k]);
        float4 w = __ldg(&wep[k]);
        dot = fmaf(a.x, w.x, dot);
        dot = fmaf(a.y, w.y, dot);
        dot = fmaf(a.z, w.z, dot);
        dot = fmaf(a.w, w.w, dot);
    }
    float gate = 1.0f / (1.0f + expf(-(dot + __ldg(be))));

    int slot = atomicAdd(&g_pos[row], 1);
    g_sedge[g_off[row] + slot] = make_int2(col, __float_as_int(gate));
}

// ---------------------------------------------------------------------------
// K5: accumulate + mean. 16 lanes per node, float4 accumulator per lane.
// Alignment prologue, then 4 edges/iter via two int4 loads (2 edges / 16B).
// ---------------------------------------------------------------------------
__global__ void __launch_bounds__(256) accum_kernel(
        float* __restrict__ out, int n_nodes) {
    const int tid = threadIdx.x;
    const int node = blockIdx.x * 16 + (tid >> 4);
    const int l = tid & 15;
    if (node >= n_nodes) return;

    const int beg = __ldg(&g_off[node]);
    const int end = __ldg(&g_off[node + 1]);

    float4 acc = make_float4(0.f, 0.f, 0.f, 0.f);
    int j = beg;

    // prologue: reach 16B (even-index) alignment of g_sedge
    if ((j & 1) && j < end) {
        int2 e0 = __ldg(&g_sedge[j]);
        float4 v0 = *reinterpret_cast<const float4*>(&g_xp[(size_t)e0.x * D + l * 4]);
        float g0 = __int_as_float(e0.y);
        acc.x = fmaf(g0, v0.x, acc.x); acc.y = fmaf(g0, v0.y, acc.y);
        acc.z = fmaf(g0, v0.z, acc.z); acc.w = fmaf(g0, v0.w, acc.w);
        j++;
    }
    const int4* eb = reinterpret_cast<const int4*>(g_sedge);
    for (; j + 3 < end; j += 4) {
        int4 p0 = __ldg(&eb[(j >> 1) + 0]);   // (col0, g0, col1, g1)
        int4 p1 = __ldg(&eb[(j >> 1) + 1]);   // (col2, g2, col3, g3)
        float4 v0 = *reinterpret_cast<const float4*>(&g_xp[(size_t)p0.x * D + l * 4]);
        float4 v1 = *reinterpret_cast<const float4*>(&g_xp[(size_t)p0.z * D + l * 4]);
        float4 v2 = *reinterpret_cast<const float4*>(&g_xp[(size_t)p1.x * D + l * 4]);
        float4 v3 = *reinterpret_cast<const float4*>(&g_xp[(size_t)p1.z * D + l * 4]);
        float g0 = __int_as_float(p0.y);
        float g1 = __int_as_float(p0.w);
        float g2 = __int_as_float(p1.y);
        float g3 = __int_as_float(p1.w);
        acc.x = fmaf(g0, v0.x, acc.x); acc.y = fmaf(g0, v0.y, acc.y);
        acc.z = fmaf(g0, v0.z, acc.z); acc.w = fmaf(g0, v0.w, acc.w);
        acc.x = fmaf(g1, v1.x, acc.x); acc.y = fmaf(g1, v1.y, acc.y);
        acc.z = fmaf(g1, v1.z, acc.z); acc.w = fmaf(g1, v1.w, acc.w);
        acc.x = fmaf(g2, v2.x, acc.x); acc.y = fmaf(g2, v2.y, acc.y);
        acc.z = fmaf(g2, v2.z, acc.z); acc.w = fmaf(g2, v2.w, acc.w);
        acc.x = fmaf(g3, v3.x, acc.x); acc.y = fmaf(g3, v3.y, acc.y);
        acc.z = fmaf(g3, v3.z, acc.z); acc.w = fmaf(g3, v3.w, acc.w);
    }
    for (; j < end; j++) {
        int2 e0 = __ldg(&g_sedge[j]);
        float4 v0 = *reinterpret_cast<const float4*>(&g_xp[(size_t)e0.x * D + l * 4]);
        float g0 = __int_as_float(e0.y);
        acc.x = fmaf(g0, v0.x, acc.x); acc.y = fmaf(g0, v0.y, acc.y);
        acc.z = fmaf(g0, v0.z, acc.z); acc.w = fmaf(g0, v0.w, acc.w);
    }

    int cnt = end - beg;
    float s = 1.0f / (float)(cnt > 1 ? cnt : 1);
    acc.x *= s; acc.y *= s; acc.z *= s; acc.w *= s;
    *reinterpret_cast<float4*>(&out[(size_t)node * D + l * 4]) = acc;
}

// ---------------------------------------------------------------------------
extern "C" void kernel_launch(void* const* d_in, const int* in_sizes, int n_in,
                              void* d_out, int out_size) {
    const float* x  = (const float*)d_in[0];       // [N,64]
    const int*   ei = (const int*)d_in[1];         // [2,E] int32
    const float* ef = (const float*)d_in[2];       // [E,16]
    const float* We = (const float*)d_in[3];       // [16]
    const float* be = (const float*)d_in[4];       // [1]
    const float* Wn = (const float*)d_in[5];       // [64,64]
    const float* bn = (const float*)d_in[6];       // [64]
    float* out = (float*)d_out;                    // [N,64] f32

    int n_nodes = in_sizes[0] / D;
    int n_edges = in_sizes[2] / ED;
    if (n_nodes > NN_CAP) n_nodes = NN_CAP;
    if (n_edges > EE_CAP) n_edges = EE_CAP;

    int nblk = (n_nodes + CHUNK - 1) / CHUNK;      // <= 196 <= 256

    init_kernel<<<(n_nodes + 255) / 256, 256>>>(n_nodes);
    gemm_xp_kernel<<<(n_nodes + 63) / 64, 256>>>(x, Wn, bn, n_nodes);
    hist_kernel<<<(n_edges + 255) / 256, 256>>>(ei, n_edges, n_nodes);
    scan_partial_kernel<<<nblk, CHUNK>>>(n_nodes);
    scan_final_kernel<<<nblk, CHUNK>>>(n_nodes);
    permute_kernel<<<(n_edges + 255) / 256, 256>>>(ei, ef, We, be, n_edges, n_nodes);
    accum_kernel<<<(n_nodes + 15) / 16, 256>>>(out, n_nodes);
}

// round 8
// speedup vs baseline: 1.0142x; 1.0142x over previous
#include <cuda_runtime.h>
#include <math.h>

#define NN_CAP 100000
#define EE_CAP 1600000
#define D      64
#define ED     16
#define CHUNK  512

// Scratch (no allocations allowed).
__device__ float g_xp[NN_CAP * D];        // projected nodes (25.6 MB)
__device__ int   g_hist[NN_CAP];          // per-node in-degree
__device__ int   g_pos[NN_CAP];           // per-node fill cursor
__device__ int   g_off[NN_CAP + 1];       // CSR offsets
__device__ int   g_state[256];            // lookback state: (aggregate<<2)|flag
__device__ int2  g_sedge[EE_CAP];         // CSR payload: (col, gate bits) (12.8 MB)

// ---------------------------------------------------------------------------
// K0: zero histogram + cursors + scan state
// ---------------------------------------------------------------------------
__global__ void init_kernel(int n_nodes) {
    int i = blockIdx.x * blockDim.x + threadIdx.x;
    if (i < n_nodes) { g_hist[i] = 0; g_pos[i] = 0; }
    if (i < 256) g_state[i] = 0;
}

// ---------------------------------------------------------------------------
// K1: xp = x @ W_node^T + b_node   (x:[N,64], W:[64,64] row-major [o][i])
// ---------------------------------------------------------------------------
__global__ void __launch_bounds__(256) gemm_xp_kernel(
        const float* __restrict__ x,
        const float* __restrict__ W,
        const float* __restrict__ b,
        int n_nodes) {
    __shared__ float Ws[64][68];  // Ws[i][o]
    __shared__ float Xs[64][68];  // Xs[i][n]

    const int tid = threadIdx.x;
    const int node0 = blockIdx.x * 64;

    #pragma unroll
    for (int t = tid; t < 64 * 16; t += 256) {
        int o = t >> 4;
        int i4 = (t & 15) << 2;
        float4 w = *reinterpret_cast<const float4*>(&W[o * 64 + i4]);
        Ws[i4 + 0][o] = w.x; Ws[i4 + 1][o] = w.y;
        Ws[i4 + 2][o] = w.z; Ws[i4 + 3][o] = w.w;
    }
    #pragma unroll
    for (int t = tid; t < 64 * 16; t += 256) {
        int n = t >> 4;
        int i4 = (t & 15) << 2;
        int gn = node0 + n;
        float4 v = make_float4(0.f, 0.f, 0.f, 0.f);
        if (gn < n_nodes)
            v = *reinterpret_cast<const float4*>(&x[gn * 64 + i4]);
        Xs[i4 + 0][n] = v.x; Xs[i4 + 1][n] = v.y;
        Xs[i4 + 2][n] = v.z; Xs[i4 + 3][n] = v.w;
    }
    __syncthreads();

    const int tx = tid & 15;
    const int ty = tid >> 4;
    const int o0 = ty * 4;
    const int n0 = tx * 4;

    float acc[4][4];
    #pragma unroll
    for (int a = 0; a < 4; a++)
        #pragma unroll
        for (int c = 0; c < 4; c++) acc[a][c] = 0.0f;

    #pragma unroll
    for (int i = 0; i < 64; i++) {
        float4 wv = *reinterpret_cast<float4*>(&Ws[i][o0]);
        float4 xv = *reinterpret_cast<float4*>(&Xs[i][n0]);
        float wr[4] = {wv.x, wv.y, wv.z, wv.w};
        float xr[4] = {xv.x, xv.y, xv.z, xv.w};
        #pragma unroll
        for (int a = 0; a < 4; a++)
            #pragma unroll
            for (int c = 0; c < 4; c++)
                acc[a][c] = fmaf(xr[a], wr[c], acc[a][c]);
    }

    float4 bv = *reinterpret_cast<const float4*>(&b[o0]);
    #pragma unroll
    for (int a = 0; a < 4; a++) {
        int gn = node0 + n0 + a;
        if (gn < n_nodes) {
            float4 r;
            r.x = acc[a][0] + bv.x; r.y = acc[a][1] + bv.y;
            r.z = acc[a][2] + bv.z; r.w = acc[a][3] + bv.w;
            *reinterpret_cast<float4*>(&g_xp[gn * 64 + o0]) = r;
        }
    }
}

// ---------------------------------------------------------------------------
// K2: histogram of destination rows (row half of ei only)
// ---------------------------------------------------------------------------
__global__ void hist_kernel(const int* __restrict__ ei, int n_edges, int n_nodes) {
    int e = blockIdx.x * blockDim.x + threadIdx.x;
    if (e >= n_edges) return;
    int row = __ldg(&ei[e]);
    if ((unsigned)row >= (unsigned)n_nodes) return;
    atomicAdd(&g_hist[row], 1);
}

// ---------------------------------------------------------------------------
// K3: single-pass scan with aggregate lookback.
// Each block: local inclusive scan of its 512-chunk, publish aggregate,
// spin-read all predecessor aggregates (one per thread), write g_off.
// All <=196 blocks are wave-1 resident; the wait DAG (b waits on k<b) is
// acyclic, so the spin cannot deadlock.
// ---------------------------------------------------------------------------
__global__ void __launch_bounds__(CHUNK) scan_kernel(int n_nodes) {
    const int tid = threadIdx.x;
    const int bid = blockIdx.x;
    const int lane = tid & 31;
    const int wid = tid >> 5;
    int i = bid * CHUNK + tid;
    int v = (i < n_nodes) ? g_hist[i] : 0;

    // inclusive warp scan
    int x = v;
    #pragma unroll
    for (int o = 1; o < 32; o <<= 1) {
        int y = __shfl_up_sync(0xffffffffu, x, o);
        if (lane >= o) x += y;
    }

    __shared__ int wsum[16];
    __shared__ int red[16];
    __shared__ int spref;
    if (lane == 31) wsum[wid] = x;
    __syncthreads();
    if (tid < 16) {
        int t = wsum[tid];
        #pragma unroll
        for (int o = 1; o < 16; o <<= 1) {
            int y = __shfl_up_sync(0xffffu, t, o, 16);
            if (tid >= o) t += y;
        }
        wsum[tid] = t;  // inclusive over warps
    }
    __syncthreads();

    const int warppref = (wid == 0) ? 0 : wsum[wid - 1];
    const int agg = wsum[15];               // block aggregate

    // publish aggregate (value packed with flag bit; single word => coherent)
    if (tid == 0) atomicExch(&g_state[bid], (agg << 2) | 1);

    // lookback: thread k (< bid) spins for predecessor k's aggregate
    int contrib = 0;
    for (int k = tid; k < bid; k += CHUNK) {
        int s;
        do { s = atomicAdd(&g_state[k], 0); } while ((s & 3) == 0);
        contrib += (s >> 2);
    }
    // block-reduce contrib
    #pragma unroll
    for (int o = 16; o; o >>= 1) contrib += __shfl_down_sync(0xffffffffu, contrib, o);
    if (lane == 0) red[wid] = contrib;
    __syncthreads();
    if (tid < 16) {
        int t = red[tid];
        #pragma unroll
        for (int o = 8; o; o >>= 1) t += __shfl_down_sync(0xffffu, t, o, 16);
        if (tid == 0) spref = t;
    }
    __syncthreads();

    int incl = x + warppref + spref;
    int excl = incl - v;
    if (i < n_nodes) {
        g_off[i] = excl;
        if (i == n_nodes - 1) g_off[n_nodes] = incl;
    }
}

// ---------------------------------------------------------------------------
// K4: permute — compute gate per edge, write (col, gate) into CSR slot.
// ---------------------------------------------------------------------------
__global__ void __launch_bounds__(256) permute_kernel(
        const int* __restrict__ ei,
        const float* __restrict__ ef,
        const float* __restrict__ We,
        const float* __restrict__ be,
        int n_edges, int n_nodes) {
    int e = blockIdx.x * blockDim.x + threadIdx.x;
    if (e >= n_edges) return;
    int row = __ldg(&ei[e]);
    int col = __ldg(&ei[n_edges + e]);
    if ((unsigned)row >= (unsigned)n_nodes || (unsigned)col >= (unsigned)n_nodes)
        return;

    const float4* efp = reinterpret_cast<const float4*>(&ef[(long long)e * ED]);
    const float4* wep = reinterpret_cast<const float4*>(We);
    float dot = 0.0f;
    #pragma unroll
    for (int k = 0; k < 4; k++) {
        float4 a = __ldg(&efp[k]);
        float4 w = __ldg(&wep[k]);
        dot = fmaf(a.x, w.x, dot);
        dot = fmaf(a.y, w.y, dot);
        dot = fmaf(a.z, w.z, dot);
        dot = fmaf(a.w, w.w, dot);
    }
    float gate = 1.0f / (1.0f + expf(-(dot + __ldg(be))));

    int slot = atomicAdd(&g_pos[row], 1);
    g_sedge[g_off[row] + slot] = make_int2(col, __float_as_int(gate));
}

// ---------------------------------------------------------------------------
// K5: accumulate + mean. 16 lanes per node, float4 accumulator per lane.
// Alignment prologue, then 4 edges/iter via two int4 loads (2 edges / 16B).
// ---------------------------------------------------------------------------
__global__ void __launch_bounds__(256) accum_kernel(
        float* __restrict__ out, int n_nodes) {
    const int tid = threadIdx.x;
    const int node = blockIdx.x * 16 + (tid >> 4);
    const int l = tid & 15;
    if (node >= n_nodes) return;

    const int beg = __ldg(&g_off[node]);
    const int end = __ldg(&g_off[node + 1]);

    float4 acc = make_float4(0.f, 0.f, 0.f, 0.f);
    int j = beg;

    if ((j & 1) && j < end) {
        int2 e0 = __ldg(&g_sedge[j]);
        float4 v0 = *reinterpret_cast<const float4*>(&g_xp[(size_t)e0.x * D + l * 4]);
        float g0 = __int_as_float(e0.y);
        acc.x = fmaf(g0, v0.x, acc.x); acc.y = fmaf(g0, v0.y, acc.y);
        acc.z = fmaf(g0, v0.z, acc.z); acc.w = fmaf(g0, v0.w, acc.w);
        j++;
    }
    const int4* eb = reinterpret_cast<const int4*>(g_sedge);
    for (; j + 3 < end; j += 4) {
        int4 p0 = __ldg(&eb[(j >> 1) + 0]);
        int4 p1 = __ldg(&eb[(j >> 1) + 1]);
        float4 v0 = *reinterpret_cast<const float4*>(&g_xp[(size_t)p0.x * D + l * 4]);
        float4 v1 = *reinterpret_cast<const float4*>(&g_xp[(size_t)p0.z * D + l * 4]);
        float4 v2 = *reinterpret_cast<const float4*>(&g_xp[(size_t)p1.x * D + l * 4]);
        float4 v3 = *reinterpret_cast<const float4*>(&g_xp[(size_t)p1.z * D + l * 4]);
        float g0 = __int_as_float(p0.y);
        float g1 = __int_as_float(p0.w);
        float g2 = __int_as_float(p1.y);
        float g3 = __int_as_float(p1.w);
        acc.x = fmaf(g0, v0.x, acc.x); acc.y = fmaf(g0, v0.y, acc.y);
        acc.z = fmaf(g0, v0.z, acc.z); acc.w = fmaf(g0, v0.w, acc.w);
        acc.x = fmaf(g1, v1.x, acc.x); acc.y = fmaf(g1, v1.y, acc.y);
        acc.z = fmaf(g1, v1.z, acc.z); acc.w = fmaf(g1, v1.w, acc.w);
        acc.x = fmaf(g2, v2.x, acc.x); acc.y = fmaf(g2, v2.y, acc.y);
        acc.z = fmaf(g2, v2.z, acc.z); acc.w = fmaf(g2, v2.w, acc.w);
        acc.x = fmaf(g3, v3.x, acc.x); acc.y = fmaf(g3, v3.y, acc.y);
        acc.z = fmaf(g3, v3.z, acc.z); acc.w = fmaf(g3, v3.w, acc.w);
    }
    for (; j < end; j++) {
        int2 e0 = __ldg(&g_sedge[j]);
        float4 v0 = *reinterpret_cast<const float4*>(&g_xp[(size_t)e0.x * D + l * 4]);
        float g0 = __int_as_float(e0.y);
        acc.x = fmaf(g0, v0.x, acc.x); acc.y = fmaf(g0, v0.y, acc.y);
        acc.z = fmaf(g0, v0.z, acc.z); acc.w = fmaf(g0, v0.w, acc.w);
    }

    int cnt = end - beg;
    float s = 1.0f / (float)(cnt > 1 ? cnt : 1);
    acc.x *= s; acc.y *= s; acc.z *= s; acc.w *= s;
    *reinterpret_cast<float4*>(&out[(size_t)node * D + l * 4]) = acc;
}

// ---------------------------------------------------------------------------
extern "C" void kernel_launch(void* const* d_in, const int* in_sizes, int n_in,
                              void* d_out, int out_size) {
    const float* x  = (const float*)d_in[0];       // [N,64]
    const int*   ei = (const int*)d_in[1];         // [2,E] int32
    const float* ef = (const float*)d_in[2];       // [E,16]
    const float* We = (const float*)d_in[3];       // [16]
    const float* be = (const float*)d_in[4];       // [1]
    const float* Wn = (const float*)d_in[5];       // [64,64]
    const float* bn = (const float*)d_in[6];       // [64]
    float* out = (float*)d_out;                    // [N,64] f32

    int n_nodes = in_sizes[0] / D;
    int n_edges = in_sizes[2] / ED;
    if (n_nodes > NN_CAP) n_nodes = NN_CAP;
    if (n_edges > EE_CAP) n_edges = EE_CAP;

    int nblk = (n_nodes + CHUNK - 1) / CHUNK;      // <= 196

    init_kernel<<<(n_nodes + 255) / 256, 256>>>(n_nodes);
    gemm_xp_kernel<<<(n_nodes + 63) / 64, 256>>>(x, Wn, bn, n_nodes);
    hist_kernel<<<(n_edges + 255) / 256, 256>>>(ei, n_edges, n_nodes);
    scan_kernel<<<nblk, CHUNK>>>(n_nodes);
    permute_kernel<<<(n_edges + 255) / 256, 256>>>(ei, ef, We, be, n_edges, n_nodes);
    accum_kernel<<<(n_nodes + 15) / 16, 256>>>(out, n_nodes);
}

// round 9
// speedup vs baseline: 1.0754x; 1.0603x over previous
#include <cuda_runtime.h>
#include <cuda_fp16.h>
#include <math.h>

#define NN_CAP 100000
#define EE_CAP 1600000
#define D      64
#define ED     16
#define CHUNK  512

// Scratch (no allocations allowed).
__device__ __half g_xp[NN_CAP * D];       // projected nodes, fp16 (12.8 MB)
__device__ int    g_hist[NN_CAP];         // per-node in-degree
__device__ int    g_pos[NN_CAP];          // per-node fill cursor
__device__ int    g_off[NN_CAP + 1];      // CSR offsets
__device__ int    g_state[256];           // lookback state: (aggregate<<2)|flag
__device__ int2   g_sedge[EE_CAP];        // CSR payload: (col, gate bits) (12.8 MB)

// ---------------------------------------------------------------------------
// K0: zero histogram + cursors + scan state
// ---------------------------------------------------------------------------
__global__ void init_kernel(int n_nodes) {
    int i = blockIdx.x * blockDim.x + threadIdx.x;
    if (i < n_nodes) { g_hist[i] = 0; g_pos[i] = 0; }
    if (i < 256) g_state[i] = 0;
}

// ---------------------------------------------------------------------------
// K1: xp = x @ W_node^T + b_node ; fp32 accumulate, fp16 store.
// ---------------------------------------------------------------------------
__global__ void __launch_bounds__(256) gemm_xp_kernel(
        const float* __restrict__ x,
        const float* __restrict__ W,
        const float* __restrict__ b,
        int n_nodes) {
    __shared__ float Ws[64][68];  // Ws[i][o]
    __shared__ float Xs[64][68];  // Xs[i][n]

    const int tid = threadIdx.x;
    const int node0 = blockIdx.x * 64;

    #pragma unroll
    for (int t = tid; t < 64 * 16; t += 256) {
        int o = t >> 4;
        int i4 = (t & 15) << 2;
        float4 w = *reinterpret_cast<const float4*>(&W[o * 64 + i4]);
        Ws[i4 + 0][o] = w.x; Ws[i4 + 1][o] = w.y;
        Ws[i4 + 2][o] = w.z; Ws[i4 + 3][o] = w.w;
    }
    #pragma unroll
    for (int t = tid; t < 64 * 16; t += 256) {
        int n = t >> 4;
        int i4 = (t & 15) << 2;
        int gn = node0 + n;
        float4 v = make_float4(0.f, 0.f, 0.f, 0.f);
        if (gn < n_nodes)
            v = *reinterpret_cast<const float4*>(&x[gn * 64 + i4]);
        Xs[i4 + 0][n] = v.x; Xs[i4 + 1][n] = v.y;
        Xs[i4 + 2][n] = v.z; Xs[i4 + 3][n] = v.w;
    }
    __syncthreads();

    const int tx = tid & 15;
    const int ty = tid >> 4;
    const int o0 = ty * 4;
    const int n0 = tx * 4;

    float acc[4][4];
    #pragma unroll
    for (int a = 0; a < 4; a++)
        #pragma unroll
        for (int c = 0; c < 4; c++) acc[a][c] = 0.0f;

    #pragma unroll
    for (int i = 0; i < 64; i++) {
        float4 wv = *reinterpret_cast<float4*>(&Ws[i][o0]);
        float4 xv = *reinterpret_cast<float4*>(&Xs[i][n0]);
        float wr[4] = {wv.x, wv.y, wv.z, wv.w};
        float xr[4] = {xv.x, xv.y, xv.z, xv.w};
        #pragma unroll
        for (int a = 0; a < 4; a++)
            #pragma unroll
            for (int c = 0; c < 4; c++)
                acc[a][c] = fmaf(xr[a], wr[c], acc[a][c]);
    }

    float4 bv = *reinterpret_cast<const float4*>(&b[o0]);
    #pragma unroll
    for (int a = 0; a < 4; a++) {
        int gn = node0 + n0 + a;
        if (gn < n_nodes) {
            __half2 h0 = __floats2half2_rn(acc[a][0] + bv.x, acc[a][1] + bv.y);
            __half2 h1 = __floats2half2_rn(acc[a][2] + bv.z, acc[a][3] + bv.w);
            uint2 u;
            u.x = *reinterpret_cast<unsigned*>(&h0);
            u.y = *reinterpret_cast<unsigned*>(&h1);
            *reinterpret_cast<uint2*>(&g_xp[gn * 64 + o0]) = u;
        }
    }
}

// ---------------------------------------------------------------------------
// K2: histogram of destination rows (row half of ei only)
// ---------------------------------------------------------------------------
__global__ void hist_kernel(const int* __restrict__ ei, int n_edges, int n_nodes) {
    int e = blockIdx.x * blockDim.x + threadIdx.x;
    if (e >= n_edges) return;
    int row = __ldg(&ei[e]);
    if ((unsigned)row >= (unsigned)n_nodes) return;
    atomicAdd(&g_hist[row], 1);
}

// ---------------------------------------------------------------------------
// K3: single-pass scan with aggregate lookback (196 wave-1-resident blocks;
// acyclic wait DAG, cannot deadlock).
// ---------------------------------------------------------------------------
__global__ void __launch_bounds__(CHUNK) scan_kernel(int n_nodes) {
    const int tid = threadIdx.x;
    const int bid = blockIdx.x;
    const int lane = tid & 31;
    const int wid = tid >> 5;
    int i = bid * CHUNK + tid;
    int v = (i < n_nodes) ? g_hist[i] : 0;

    int x = v;
    #pragma unroll
    for (int o = 1; o < 32; o <<= 1) {
        int y = __shfl_up_sync(0xffffffffu, x, o);
        if (lane >= o) x += y;
    }

    __shared__ int wsum[16];
    __shared__ int red[16];
    __shared__ int spref;
    if (lane == 31) wsum[wid] = x;
    __syncthreads();
    if (tid < 16) {
        int t = wsum[tid];
        #pragma unroll
        for (int o = 1; o < 16; o <<= 1) {
            int y = __shfl_up_sync(0xffffu, t, o, 16);
            if (tid >= o) t += y;
        }
        wsum[tid] = t;
    }
    __syncthreads();

    const int warppref = (wid == 0) ? 0 : wsum[wid - 1];
    const int agg = wsum[15];

    if (tid == 0) atomicExch(&g_state[bid], (agg << 2) | 1);

    int contrib = 0;
    for (int k = tid; k < bid; k += CHUNK) {
        int s;
        do { s = atomicAdd(&g_state[k], 0); } while ((s & 3) == 0);
        contrib += (s >> 2);
    }
    #pragma unroll
    for (int o = 16; o; o >>= 1) contrib += __shfl_down_sync(0xffffffffu, contrib, o);
    if (lane == 0) red[wid] = contrib;
    __syncthreads();
    if (tid < 16) {
        int t = red[tid];
        #pragma unroll
        for (int o = 8; o; o >>= 1) t += __shfl_down_sync(0xffffu, t, o, 16);
        if (tid == 0) spref = t;
    }
    __syncthreads();

    int incl = x + warppref + spref;
    int excl = incl - v;
    if (i < n_nodes) {
        g_off[i] = excl;
        if (i == n_nodes - 1) g_off[n_nodes] = incl;
    }
}

// ---------------------------------------------------------------------------
// K4: permute — compute gate per edge, write (col, gate) into CSR slot.
// ---------------------------------------------------------------------------
__global__ void __launch_bounds__(256) permute_kernel(
        const int* __restrict__ ei,
        const float* __restrict__ ef,
        const float* __restrict__ We,
        const float* __restrict__ be,
        int n_edges, int n_nodes) {
    int e = blockIdx.x * blockDim.x + threadIdx.x;
    if (e >= n_edges) return;
    int row = __ldg(&ei[e]);
    int col = __ldg(&ei[n_edges + e]);
    if ((unsigned)row >= (unsigned)n_nodes || (unsigned)col >= (unsigned)n_nodes)
        return;

    const float4* efp = reinterpret_cast<const float4*>(&ef[(long long)e * ED]);
    const float4* wep = reinterpret_cast<const float4*>(We);
    float dot = 0.0f;
    #pragma unroll
    for (int k = 0; k < 4; k++) {
        float4 a = __ldg(&efp[k]);
        float4 w = __ldg(&wep[k]);
        dot = fmaf(a.x, w.x, dot);
        dot = fmaf(a.y, w.y, dot);
        dot = fmaf(a.z, w.z, dot);
        dot = fmaf(a.w, w.w, dot);
    }
    float gate = 1.0f / (1.0f + expf(-(dot + __ldg(be))));

    int slot = atomicAdd(&g_pos[row], 1);
    g_sedge[g_off[row] + slot] = make_int2(col, __float_as_int(gate));
}

// ---------------------------------------------------------------------------
// K5: accumulate + mean. 16 lanes per node; lane l covers cols [4l,4l+4).
// fp16 gathers (uint2 = 4 halves), fp32 accumulate. 4 edges/iter.
// ---------------------------------------------------------------------------
__device__ __forceinline__ void acc_edge(float4& acc, int col, float g, int l) {
    uint2 q = *reinterpret_cast<const uint2*>(&g_xp[(size_t)col * D + l * 4]);
    float2 f0 = __half22float2(*reinterpret_cast<__half2*>(&q.x));
    float2 f1 = __half22float2(*reinterpret_cast<__half2*>(&q.y));
    acc.x = fmaf(g, f0.x, acc.x);
    acc.y = fmaf(g, f0.y, acc.y);
    acc.z = fmaf(g, f1.x, acc.z);
    acc.w = fmaf(g, f1.y, acc.w);
}

__global__ void __launch_bounds__(256) accum_kernel(
        float* __restrict__ out, int n_nodes) {
    const int tid = threadIdx.x;
    const int node = blockIdx.x * 16 + (tid >> 4);
    const int l = tid & 15;
    if (node >= n_nodes) return;

    const int beg = __ldg(&g_off[node]);
    const int end = __ldg(&g_off[node + 1]);

    float4 acc = make_float4(0.f, 0.f, 0.f, 0.f);
    int j = beg;

    if ((j & 1) && j < end) {
        int2 e0 = __ldg(&g_sedge[j]);
        acc_edge(acc, e0.x, __int_as_float(e0.y), l);
        j++;
    }
    const int4* eb = reinterpret_cast<const int4*>(g_sedge);
    for (; j + 3 < end; j += 4) {
        int4 p0 = __ldg(&eb[(j >> 1) + 0]);   // (col0, g0, col1, g1)
        int4 p1 = __ldg(&eb[(j >> 1) + 1]);   // (col2, g2, col3, g3)
        acc_edge(acc, p0.x, __int_as_float(p0.y), l);
        acc_edge(acc, p0.z, __int_as_float(p0.w), l);
        acc_edge(acc, p1.x, __int_as_float(p1.y), l);
        acc_edge(acc, p1.z, __int_as_float(p1.w), l);
    }
    for (; j < end; j++) {
        int2 e0 = __ldg(&g_sedge[j]);
        acc_edge(acc, e0.x, __int_as_float(e0.y), l);
    }

    int cnt = end - beg;
    float s = 1.0f / (float)(cnt > 1 ? cnt : 1);
    acc.x *= s; acc.y *= s; acc.z *= s; acc.w *= s;
    *reinterpret_cast<float4*>(&out[(size_t)node * D + l * 4]) = acc;
}

// ---------------------------------------------------------------------------
extern "C" void kernel_launch(void* const* d_in, const int* in_sizes, int n_in,
                              void* d_out, int out_size) {
    const float* x  = (const float*)d_in[0];       // [N,64]
    const int*   ei = (const int*)d_in[1];         // [2,E] int32
    const float* ef = (const float*)d_in[2];       // [E,16]
    const float* We = (const float*)d_in[3];       // [16]
    const float* be = (const float*)d_in[4];       // [1]
    const float* Wn = (const float*)d_in[5];       // [64,64]
    const float* bn = (const float*)d_in[6];       // [64]
    float* out = (float*)d_out;                    // [N,64] f32

    int n_nodes = in_sizes[0] / D;
    int n_edges = in_sizes[2] / ED;
    if (n_nodes > NN_CAP) n_nodes = NN_CAP;
    if (n_edges > EE_CAP) n_edges = EE_CAP;

    int nblk = (n_nodes + CHUNK - 1) / CHUNK;      // <= 196

    init_kernel<<<(n_nodes + 255) / 256, 256>>>(n_nodes);
    gemm_xp_kernel<<<(n_nodes + 63) / 64, 256>>>(x, Wn, bn, n_nodes);
    hist_kernel<<<(n_edges + 255) / 256, 256>>>(ei, n_edges, n_nodes);
    scan_kernel<<<nblk, CHUNK>>>(n_nodes);
    permute_kernel<<<(n_edges + 255) / 256, 256>>>(ei, ef, We, be, n_edges, n_nodes);
    accum_kernel<<<(n_nodes + 15) / 16, 256>>>(out, n_nodes);
}